// round 8
// baseline (speedup 1.0000x reference)
#include <cuda_runtime.h>
#include <cuda_fp16.h>
#include <cstdint>
#include <math.h>

#define N_ATOMS  10000
#define N_STRUCT 100
#define NPSEUDO  4
#define NSPECIES 4
#define NFEAT    4096
#define HIDDEN   256
#define NPACK    2112            // 4 * 528 triangular packing
#define KT0      (NPACK / 32)    // 66 k-tiles of 32
#define KT1      (HIDDEN / 32)   // 8
#define MBLK     79              // ceil(10000/128)
#define APAD     (MBLK * 128)    // 10112

// ---------------- scratch (static device globals; no allocation) ----------------
// fp16 fragment-major A (features): [b128][kt][b16(8)][kmma(2)][lane(32)][reg(4)] u32
__device__ uint32_t g_featP[(size_t)MBLK * KT0 * 2048];               // 42.7 MB
// fp16 fragment-major B (W0 symmetrized): [p][kt][nt(32)][kmma(2)][lane(32)][khalf(2)] u32
__device__ uint32_t g_W0f[(size_t)NPSEUDO * KT0 * 4096];              // 4.3 MB
__device__ uint32_t g_W1f[(size_t)NPSEUDO * KT1 * 4096];              // 0.5 MB
// fp16 fragment-major h1 (A of GEMM1): [p][b128][kt(8)][b16(8)][kmma(2)][lane(32)][reg(4)]
__device__ uint32_t g_h1f[(size_t)NPSEUDO * MBLK * KT1 * 2048];       // 20.7 MB
__device__ __half   g_h2h[(size_t)NPSEUDO * N_ATOMS * HIDDEN];        // 20.5 MB

__device__ __forceinline__ float silu(float x) { return x / (1.0f + expf(-x)); }

__device__ __forceinline__ uint32_t smem_u32(const void* p) {
    uint32_t a;
    asm("{ .reg .u64 t; cvta.to.shared.u64 t, %1; cvt.u32.u64 %0, t; }" : "=r"(a) : "l"(p));
    return a;
}

// triangular decode: t2 in [0,528) -> (q, r), q<=r<32
__device__ __forceinline__ void tri_decode(int t2, int& q, int& r) {
    q = (int)((65.0f - sqrtf(4225.0f - 8.0f * (float)t2)) * 0.5f);
    if (q < 0) q = 0;
    while (q * (65 - q) / 2 > t2) q--;
    while ((q + 1) * (64 - q) / 2 <= t2) q++;
    r = q + (t2 - q * (65 - q) / 2);
}

// B-fragment halfword offset for element (k within 32-tile, col c within 256)
__device__ __forceinline__ size_t b_frag_off(int kt, int kin, int c, int ktiles, int p) {
    int kmma = kin >> 4, k16 = kin & 15;
    int khalf = k16 >> 3, kpos = k16 & 7;
    int tig = kpos >> 1, hw = kpos & 1;
    int nt = c >> 3, grp = c & 7, lane = grp * 4 + tig;
    size_t idx = (size_t)(p * ktiles + kt);
    idx = idx * 32 + nt;
    idx = idx * 2 + kmma;
    idx = idx * 32 + lane;
    idx = idx * 2 + khalf;
    return idx * 2 + hw;
}

// ---------------- W0: symmetrize + fp16 fragment-permute ----------------
__global__ void convert_w0_kernel(const float* __restrict__ W0) {
    const int c = threadIdx.x;               // hidden col
    const int k = blockIdx.x;                // packed k 0..2111
    const int p = blockIdx.y;
    const int l = k / 528;
    const int t2 = k - l * 528;
    int q, r;
    tri_decode(t2, q, r);
    const size_t base = (size_t)p * NFEAT * HIDDEN;
    float v = W0[base + (size_t)(l * 1024 + q * 32 + r) * HIDDEN + c];
    if (q != r) v += W0[base + (size_t)(l * 1024 + r * 32 + q) * HIDDEN + c];
    ((__half*)g_W0f)[b_frag_off(k >> 5, k & 31, c, KT0, p)] = __float2half_rn(v);
}

// ---------------- W1: fp16 fragment-permute ----------------
__global__ void convert_w1_kernel(const float* __restrict__ W1) {
    const int c = threadIdx.x;
    const int k = blockIdx.x;                // 0..255
    const int p = blockIdx.y;
    float v = W1[((size_t)p * HIDDEN + k) * HIDDEN + c];
    ((__half*)g_W1f)[b_frag_off(k >> 5, k & 31, c, KT1, p)] = __float2half_rn(v);
}

// ---------------- packed power spectrum -> fp16 fragment-major features ----------------
__global__ void features_kernel(const float* __restrict__ c0,
                                const float* __restrict__ c1,
                                const float* __restrict__ c2,
                                const float* __restrict__ c3) {
    __shared__ float sc[512];
    const int a = blockIdx.x;
    const int t = threadIdx.x;
    const bool valid = (a < N_ATOMS);
    if (valid) {
        #pragma unroll
        for (int j = 0; j < 2; j++) {
            int idx = t + 256 * j;
            float v;
            if (idx < 32)        v = c0[(size_t)a * 32  + idx];
            else if (idx < 128)  v = c1[(size_t)a * 96  + (idx - 32)];
            else if (idx < 288)  v = c2[(size_t)a * 160 + (idx - 128)];
            else                 v = c3[(size_t)a * 224 + (idx - 288)];
            sc[idx] = v;
        }
        __syncthreads();
    }
    const int   loff[4] = {0, 32, 128, 288};
    const float cg[4]   = {1.0f, 0.57735026919f, 0.44721359550f, 0.37796447301f};

    const int b128 = a >> 7, row = a & 127;
    const int b16 = row >> 4, r16 = row & 15;
    const int grp = r16 & 7, rhalf = r16 >> 3;

    #pragma unroll
    for (int j = 0; j < 9; j++) {
        int k = t + 256 * j;
        if (k < NPACK) {
            float val = 0.0f;
            if (valid) {
                int l  = k / 528;
                int t2 = k - l * 528;
                int q, r;
                tri_decode(t2, q, r);
                const float* cl = sc + loff[l];
                int nm = 2 * l + 1;
                float s = 0.0f;
                for (int m = 0; m < nm; m++) s += cl[m * 32 + q] * cl[m * 32 + r];
                val = cg[l] * s;
            }
            int kt = k >> 5, kin = k & 31;
            int kmma = kin >> 4, k16 = kin & 15;
            int khalf = k16 >> 3, kpos = k16 & 7;
            int tig = kpos >> 1, hw = kpos & 1;
            int lane = grp * 4 + tig;
            int areg = rhalf + 2 * khalf;
            size_t idx = (size_t)(b128 * KT0 + kt);
            idx = idx * 8 + b16;
            idx = idx * 2 + kmma;
            idx = idx * 32 + lane;
            idx = idx * 4 + areg;
            idx = idx * 2 + hw;
            ((__half*)g_featP)[idx] = __float2half_rn(val);
        }
    }
}

// ---------------- fp16 mma (fp32 accumulate) ----------------
__device__ __forceinline__ void mma_f16(float c[4], const uint32_t a[4], const uint32_t b[2]) {
    asm volatile(
        "mma.sync.aligned.m16n8k16.row.col.f32.f16.f16.f32 "
        "{%0,%1,%2,%3}, {%4,%5,%6,%7}, {%8,%9}, {%0,%1,%2,%3};\n"
        : "+f"(c[0]), "+f"(c[1]), "+f"(c[2]), "+f"(c[3])
        : "r"(a[0]), "r"(a[1]), "r"(a[2]), "r"(a[3]), "r"(b[0]), "r"(b[1]));
}

// ================= unified fp16 GEMM: 128x128 tile, CTA=128 threads (4 warps) =================
// warp tile 64x64: 4 m16-blocks x 8 n8-blocks, acc = 128 regs.
// MODE 0: A=featP, B=W0f, C=g_h1f (fragment-major fp16), epi silu(pw*x). KT=66.
// MODE 1: A=g_h1f, B=W1f, C=g_h2h (plain fp16),          epi silu(x).    KT=8.
#define G_STFL   4096                        // u32 per stage: A 2048 + B 2048 (16KB)
#define G_STAGES 4
#define G_DSMEM  (G_STAGES * G_STFL * 4)     // 64KB

template<int KT, int MODE>
__global__ void __launch_bounds__(128, 2)
gemm_f16_kernel(const float* __restrict__ combW, const int* __restrict__ species) {
    extern __shared__ uint32_t smu[];

    const int p    = blockIdx.x >> 1;
    const int nh   = blockIdx.x & 1;
    const int b128 = blockIdx.y;
    const int m0   = b128 * 128;

    const uint32_t* Ag = (MODE == 0)
        ? g_featP + (size_t)b128 * KT0 * 2048
        : g_h1f   + (size_t)(p * MBLK + b128) * (KT1 * 2048);
    const uint32_t* Bg = ((MODE == 0) ? g_W0f + (size_t)p * KT0 * 4096
                                      : g_W1f + (size_t)p * KT1 * 4096) + nh * 2048;

    const int tid   = threadIdx.x;
    const int warp  = tid >> 5;
    const int lane  = tid & 31;
    const int grp   = lane >> 2;
    const int tig   = lane & 3;
    const int mhalf = warp & 1;          // M half: b16 = mhalf*4 + mt
    const int nhalf = warp >> 1;         // N half within CTA: nt = nhalf*8 + j

    float acc[4][8][4];
    #pragma unroll
    for (int mt = 0; mt < 4; mt++)
        #pragma unroll
        for (int nt = 0; nt < 8; nt++)
            #pragma unroll
            for (int i = 0; i < 4; i++) acc[mt][nt][i] = 0.0f;

    const uint32_t sbase = smem_u32(smu);

    // 16KB linear copy per k-tile: 1024 x 16B, 8 per thread
    auto load_tile = [&](int kt, int b) {
        const uint4* srcA = (const uint4*)(Ag + (size_t)kt * 2048);
        const uint4* srcB = (const uint4*)(Bg + (size_t)kt * 4096);
        const uint32_t dst0 = sbase + (uint32_t)b * (G_STFL * 4);
        #pragma unroll
        for (int j = 0; j < 8; j++) {
            int c = tid + 128 * j;
            const uint4* src = (c < 512) ? (srcA + c) : (srcB + (c - 512));
            uint32_t dst = dst0 + (uint32_t)c * 16u;
            asm volatile("cp.async.ca.shared.global [%0], [%1], 16;\n"
                         :: "r"(dst), "l"(src));
        }
        asm volatile("cp.async.commit_group;\n");
    };

    load_tile(0, 0);
    load_tile(1, 1);
    load_tile(2, 2);

    for (int kt = 0; kt < KT; kt++) {
        const int b = kt & (G_STAGES - 1);
        if (kt + 2 < KT)      asm volatile("cp.async.wait_group 2;\n");
        else if (kt + 1 < KT) asm volatile("cp.async.wait_group 1;\n");
        else                  asm volatile("cp.async.wait_group 0;\n");
        __syncthreads();
        if (kt + 3 < KT) load_tile(kt + 3, (kt + 3) & (G_STAGES - 1));

        const uint4* As4 = (const uint4*)(smu + (size_t)b * G_STFL);          // A: [b16][km][lane] uint4
        const uint2* Bs2 = (const uint2*)(smu + (size_t)b * G_STFL + 2048);   // B: [nt][km][lane] uint2

        // preload ALL fragments for this k-tile (24 wide LDS), then 64 HMMA
        uint4 av[4][2];
        uint2 bv[8][2];
        #pragma unroll
        for (int mt = 0; mt < 4; mt++)
            #pragma unroll
            for (int km = 0; km < 2; km++)
                av[mt][km] = As4[((mhalf * 4 + mt) * 2 + km) * 32 + lane];
        #pragma unroll
        for (int j = 0; j < 8; j++)
            #pragma unroll
            for (int km = 0; km < 2; km++)
                bv[j][km] = Bs2[((nhalf * 8 + j) * 2 + km) * 32 + lane];

        #pragma unroll
        for (int km = 0; km < 2; km++)
            #pragma unroll
            for (int j = 0; j < 8; j++) {
                const uint32_t* bf = (const uint32_t*)&bv[j][km];
                #pragma unroll
                for (int mt = 0; mt < 4; mt++)
                    mma_f16(acc[mt][j], (const uint32_t*)&av[mt][km], bf);
            }
        __syncthreads();
    }

    // ---------------- epilogue ----------------
    #pragma unroll
    for (int mt = 0; mt < 4; mt++) {
        const int b16 = mhalf * 4 + mt;
        const int r0 = m0 + b16 * 16 + grp;
        const int r1 = r0 + 8;
        float pw0 = 1.0f, pw1 = 1.0f;
        if (MODE == 0) {
            pw0 = (r0 < N_ATOMS) ? combW[p * NSPECIES + species[r0]] : 0.0f;
            pw1 = (r1 < N_ATOMS) ? combW[p * NSPECIES + species[r1]] : 0.0f;
        }
        #pragma unroll
        for (int j = 0; j < 8; j++) {
            const int c = nh * 128 + (nhalf * 8 + j) * 8 + tig * 2;  // global hidden col
            float x0 = silu(acc[mt][j][0] * pw0);
            float x1 = silu(acc[mt][j][1] * pw0);
            float x2 = silu(acc[mt][j][2] * pw1);
            float x3 = silu(acc[mt][j][3] * pw1);
            __half2 v01 = __floats2half2_rn(x0, x1);
            __half2 v23 = __floats2half2_rn(x2, x3);
            if (MODE == 0) {
                // write straight into fragment-major h1 (A of GEMM1)
                const int kt1 = c >> 5, kmma = (c >> 4) & 1, khalf = (c >> 3) & 1;
                size_t idx = (size_t)(p * MBLK + b128) * (KT1 * 2048);
                size_t sub = (size_t)(kt1 * 8 + b16);
                sub = sub * 2 + kmma;
                sub = sub * 32 + lane;
                uint32_t* base = g_h1f + idx + sub * 4;
                base[2 * khalf    ] = *(uint32_t*)&v01;
                base[2 * khalf + 1] = *(uint32_t*)&v23;
            } else {
                __half* C = g_h2h + (size_t)p * N_ATOMS * HIDDEN;
                if (r0 < N_ATOMS) *(uint32_t*)&C[(size_t)r0 * HIDDEN + c] = *(uint32_t*)&v01;
                if (r1 < N_ATOMS) *(uint32_t*)&C[(size_t)r1 * HIDDEN + c] = *(uint32_t*)&v23;
            }
        }
    }
}

// ---------------- final dot + segment sum ----------------
__global__ void zero_out_kernel(float* out) {
    if (threadIdx.x < N_STRUCT) out[threadIdx.x] = 0.0f;
}

__global__ void reduce_kernel(const float* __restrict__ W2,
                              const int* __restrict__ sid,
                              float* __restrict__ out) {
    const int a = blockIdx.x;
    const int t = threadIdx.x;
    float v = 0.0f;
    #pragma unroll
    for (int p = 0; p < NPSEUDO; p++)
        v += __half2float(g_h2h[((size_t)p * N_ATOMS + a) * HIDDEN + t]) * W2[p * HIDDEN + t];

    __shared__ float red[8];
    #pragma unroll
    for (int o = 16; o > 0; o >>= 1) v += __shfl_down_sync(0xffffffffu, v, o);
    if ((t & 31) == 0) red[t >> 5] = v;
    __syncthreads();
    if (t < 8) {
        float s = red[t];
        #pragma unroll
        for (int o = 4; o > 0; o >>= 1) s += __shfl_down_sync(0xffu, s, o);
        if (t == 0) atomicAdd(&out[sid[a]], s);
    }
}

// ---------------- launch ----------------
extern "C" void kernel_launch(void* const* d_in, const int* in_sizes, int n_in,
                              void* d_out, int out_size) {
    const float* c0      = (const float*)d_in[0];
    const float* c1      = (const float*)d_in[1];
    const float* c2      = (const float*)d_in[2];
    const float* c3      = (const float*)d_in[3];
    const int*   species = (const int*)d_in[4];
    const int*   sid     = (const int*)d_in[5];
    const float* combW   = (const float*)d_in[6];
    const float* W0      = (const float*)d_in[7];
    const float* W1      = (const float*)d_in[8];
    const float* W2      = (const float*)d_in[9];
    float* out = (float*)d_out;

    static bool attr_set = false;
    if (!attr_set) {
        cudaFuncSetAttribute(gemm_f16_kernel<KT0, 0>,
                             cudaFuncAttributeMaxDynamicSharedMemorySize, G_DSMEM);
        cudaFuncSetAttribute(gemm_f16_kernel<KT1, 1>,
                             cudaFuncAttributeMaxDynamicSharedMemorySize, G_DSMEM);
        attr_set = true;
    }

    {
        dim3 g(NPACK, NPSEUDO);
        convert_w0_kernel<<<g, 256>>>(W0);
    }
    {
        dim3 g(HIDDEN, NPSEUDO);
        convert_w1_kernel<<<g, 256>>>(W1);
    }

    features_kernel<<<APAD, 256>>>(c0, c1, c2, c3);

    {
        dim3 g(NPSEUDO * 2, MBLK);
        gemm_f16_kernel<KT0, 0><<<g, 128, G_DSMEM>>>(combW, species);
        gemm_f16_kernel<KT1, 1><<<g, 128, G_DSMEM>>>(combW, species);
    }

    zero_out_kernel<<<1, 128>>>(out);
    reduce_kernel<<<N_ATOMS, 256>>>(W2, sid, out);
}

// round 9
// speedup vs baseline: 1.1162x; 1.1162x over previous
#include <cuda_runtime.h>
#include <cuda_fp16.h>
#include <cstdint>
#include <math.h>

#define N_ATOMS  10000
#define N_STRUCT 100
#define NPSEUDO  4
#define NSPECIES 4
#define NFEAT    4096
#define HIDDEN   256
#define NPACK    2112            // 4 * 528 triangular packing
#define KT0      (NPACK / 32)    // 66 k-tiles of 32
#define KT1      (HIDDEN / 32)   // 8
#define MBLK64   157             // ceil(10000/64)
#define APAD     (MBLK64 * 64)   // 10048

// ---------------- scratch (static device globals; no allocation) ----------------
// fp16 fragment-major A (features): [b64][kt][b16(4)][kmma(2)][lane(32)][reg(4)] u32
__device__ uint32_t g_featP[(size_t)MBLK64 * KT0 * 1024];             // 42.4 MB
// fp16 fragment-major B (W0 symmetrized): [p][kt][nt(32)][kmma(2)][lane(32)][khalf(2)] u32
__device__ uint32_t g_W0f[(size_t)NPSEUDO * KT0 * 4096];              // 4.3 MB
__device__ uint32_t g_W1f[(size_t)NPSEUDO * KT1 * 4096];              // 0.5 MB
// fp16 fragment-major h1 (A of GEMM1): [p][b64][kt(8)][b16(4)][kmma(2)][lane(32)][reg(4)]
__device__ uint32_t g_h1f[(size_t)NPSEUDO * MBLK64 * KT1 * 1024];     // 20.6 MB
__device__ __half   g_h2h[(size_t)NPSEUDO * N_ATOMS * HIDDEN];        // 20.5 MB

__device__ __forceinline__ float silu(float x) { return x / (1.0f + expf(-x)); }

__device__ __forceinline__ uint32_t smem_u32(const void* p) {
    uint32_t a;
    asm("{ .reg .u64 t; cvta.to.shared.u64 t, %1; cvt.u32.u64 %0, t; }" : "=r"(a) : "l"(p));
    return a;
}

// triangular decode: t2 in [0,528) -> (q, r), q<=r<32
__device__ __forceinline__ void tri_decode(int t2, int& q, int& r) {
    q = (int)((65.0f - sqrtf(4225.0f - 8.0f * (float)t2)) * 0.5f);
    if (q < 0) q = 0;
    while (q * (65 - q) / 2 > t2) q--;
    while ((q + 1) * (64 - q) / 2 <= t2) q++;
    r = q + (t2 - q * (65 - q) / 2);
}

// B-fragment halfword offset for element (k within 32-tile, col c within 256)
__device__ __forceinline__ size_t b_frag_off(int kt, int kin, int c, int ktiles, int p) {
    int kmma = kin >> 4, k16 = kin & 15;
    int khalf = k16 >> 3, kpos = k16 & 7;
    int tig = kpos >> 1, hw = kpos & 1;
    int nt = c >> 3, grp = c & 7, lane = grp * 4 + tig;
    size_t idx = (size_t)(p * ktiles + kt);
    idx = idx * 32 + nt;
    idx = idx * 2 + kmma;
    idx = idx * 32 + lane;
    idx = idx * 2 + khalf;
    return idx * 2 + hw;
}

// ---------------- W0: symmetrize + fp16 fragment-permute ----------------
__global__ void convert_w0_kernel(const float* __restrict__ W0) {
    const int c = threadIdx.x;               // hidden col
    const int k = blockIdx.x;                // packed k 0..2111
    const int p = blockIdx.y;
    const int l = k / 528;
    const int t2 = k - l * 528;
    int q, r;
    tri_decode(t2, q, r);
    const size_t base = (size_t)p * NFEAT * HIDDEN;
    float v = W0[base + (size_t)(l * 1024 + q * 32 + r) * HIDDEN + c];
    if (q != r) v += W0[base + (size_t)(l * 1024 + r * 32 + q) * HIDDEN + c];
    ((__half*)g_W0f)[b_frag_off(k >> 5, k & 31, c, KT0, p)] = __float2half_rn(v);
}

// ---------------- W1: fp16 fragment-permute ----------------
__global__ void convert_w1_kernel(const float* __restrict__ W1) {
    const int c = threadIdx.x;
    const int k = blockIdx.x;                // 0..255
    const int p = blockIdx.y;
    float v = W1[((size_t)p * HIDDEN + k) * HIDDEN + c];
    ((__half*)g_W1f)[b_frag_off(k >> 5, k & 31, c, KT1, p)] = __float2half_rn(v);
}

// ---------------- packed power spectrum -> fp16 fragment-major features ----------------
__global__ void features_kernel(const float* __restrict__ c0,
                                const float* __restrict__ c1,
                                const float* __restrict__ c2,
                                const float* __restrict__ c3) {
    __shared__ float sc[512];
    const int a = blockIdx.x;
    const int t = threadIdx.x;
    const bool valid = (a < N_ATOMS);
    if (valid) {
        #pragma unroll
        for (int j = 0; j < 2; j++) {
            int idx = t + 256 * j;
            float v;
            if (idx < 32)        v = c0[(size_t)a * 32  + idx];
            else if (idx < 128)  v = c1[(size_t)a * 96  + (idx - 32)];
            else if (idx < 288)  v = c2[(size_t)a * 160 + (idx - 128)];
            else                 v = c3[(size_t)a * 224 + (idx - 288)];
            sc[idx] = v;
        }
        __syncthreads();
    }
    const int   loff[4] = {0, 32, 128, 288};
    const float cg[4]   = {1.0f, 0.57735026919f, 0.44721359550f, 0.37796447301f};

    const int b64 = a >> 6, row = a & 63;
    const int b16 = row >> 4, r16 = row & 15;
    const int grp = r16 & 7, rhalf = r16 >> 3;

    #pragma unroll
    for (int j = 0; j < 9; j++) {
        int k = t + 256 * j;
        if (k < NPACK) {
            float val = 0.0f;
            if (valid) {
                int l  = k / 528;
                int t2 = k - l * 528;
                int q, r;
                tri_decode(t2, q, r);
                const float* cl = sc + loff[l];
                int nm = 2 * l + 1;
                float s = 0.0f;
                for (int m = 0; m < nm; m++) s += cl[m * 32 + q] * cl[m * 32 + r];
                val = cg[l] * s;
            }
            int kt = k >> 5, kin = k & 31;
            int kmma = kin >> 4, k16 = kin & 15;
            int khalf = k16 >> 3, kpos = k16 & 7;
            int tig = kpos >> 1, hw = kpos & 1;
            int lane = grp * 4 + tig;
            int areg = rhalf + 2 * khalf;
            size_t idx = (size_t)(b64 * KT0 + kt);
            idx = idx * 4 + b16;
            idx = idx * 2 + kmma;
            idx = idx * 32 + lane;
            idx = idx * 4 + areg;
            idx = idx * 2 + hw;
            ((__half*)g_featP)[idx] = __float2half_rn(val);
        }
    }
}

// ---------------- fp16 mma (fp32 accumulate) ----------------
__device__ __forceinline__ void mma_f16(float c[4], const uint32_t a[4], const uint32_t b[2]) {
    asm volatile(
        "mma.sync.aligned.m16n8k16.row.col.f32.f16.f16.f32 "
        "{%0,%1,%2,%3}, {%4,%5,%6,%7}, {%8,%9}, {%0,%1,%2,%3};\n"
        : "+f"(c[0]), "+f"(c[1]), "+f"(c[2]), "+f"(c[3])
        : "r"(a[0]), "r"(a[1]), "r"(a[2]), "r"(a[3]), "r"(b[0]), "r"(b[1]));
}

// ================= unified fp16 GEMM: 64x128 tile, CTA=128 threads, 4 CTAs/SM =================
// MODE 0: A=featP, B=W0f, C=g_h1f (fragment-major fp16), epi silu(pw*x). KT=66.
// MODE 1: A=g_h1f, B=W1f, C=g_h2h (plain fp16),          epi silu(x).    KT=8.
#define G_STFL   3072                        // u32 per stage: A 1024 + B 2048 (12KB)
#define G_STAGES 4
#define G_DSMEM  (G_STAGES * G_STFL * 4)     // 48KB

template<int KT, int MODE>
__global__ void __launch_bounds__(128, 4)
gemm_f16_kernel(const float* __restrict__ combW, const int* __restrict__ species) {
    extern __shared__ uint32_t smu[];

    const int p   = blockIdx.x >> 1;
    const int nh  = blockIdx.x & 1;
    const int b64 = blockIdx.y;
    const int m0  = b64 * 64;

    const uint32_t* Ag = (MODE == 0)
        ? g_featP + (size_t)b64 * KT0 * 1024
        : g_h1f   + (size_t)(p * MBLK64 + b64) * (KT1 * 1024);
    const uint32_t* Bg = ((MODE == 0) ? g_W0f + (size_t)p * KT0 * 4096
                                      : g_W1f + (size_t)p * KT1 * 4096) + nh * 2048;

    const int tid  = threadIdx.x;
    const int warp = tid >> 5;
    const int lane = tid & 31;
    const int grp  = lane >> 2;
    const int tig  = lane & 3;
    const int wmB  = (warp & 1) * 2;     // m16-block base (2 per warp)
    const int wnB  = (warp >> 1) * 8;    // n8-block base within 16 (8 per warp)

    float acc[2][8][4];
    #pragma unroll
    for (int mt = 0; mt < 2; mt++)
        #pragma unroll
        for (int nt = 0; nt < 8; nt++)
            #pragma unroll
            for (int i = 0; i < 4; i++) acc[mt][nt][i] = 0.0f;

    const uint32_t sbase = smem_u32(smu);

    // 12KB linear copy per k-tile: 768 x 16B, 6 per thread
    auto load_tile = [&](int kt, int b) {
        const uint4* srcA = (const uint4*)(Ag + (size_t)kt * 1024);
        const uint4* srcB = (const uint4*)(Bg + (size_t)kt * 4096);
        const uint32_t dst0 = sbase + (uint32_t)b * (G_STFL * 4);
        #pragma unroll
        for (int j = 0; j < 6; j++) {
            int c = tid + 128 * j;
            const uint4* src = (c < 256) ? (srcA + c) : (srcB + (c - 256));
            uint32_t dst = dst0 + (uint32_t)c * 16u;
            asm volatile("cp.async.ca.shared.global [%0], [%1], 16;\n"
                         :: "r"(dst), "l"(src));
        }
        asm volatile("cp.async.commit_group;\n");
    };

    // prefetch distance 2 into a 4-deep ring; ONE barrier per k-tile.
    load_tile(0, 0);
    load_tile(1, 1);

    for (int kt = 0; kt < KT; kt++) {
        const int b = kt & (G_STAGES - 1);
        if (kt + 1 < KT) asm volatile("cp.async.wait_group 1;\n");
        else             asm volatile("cp.async.wait_group 0;\n");
        __syncthreads();
        if (kt + 2 < KT) load_tile(kt + 2, (kt + 2) & (G_STAGES - 1));

        const uint32_t* As = smu + (size_t)b * G_STFL;
        const uint32_t* Bs = As + 1024;

        #pragma unroll
        for (int km = 0; km < 2; km++) {
            uint4 a0 = *(const uint4*)(As + ((wmB    ) * 2 + km) * 128 + lane * 4);
            uint4 a1 = *(const uint4*)(As + ((wmB + 1) * 2 + km) * 128 + lane * 4);
            uint2 bv[8];
            #pragma unroll
            for (int nt = 0; nt < 8; nt++)
                bv[nt] = *(const uint2*)(Bs + ((wnB + nt) * 2 + km) * 64 + lane * 2);
            const uint32_t* af0 = (const uint32_t*)&a0;
            const uint32_t* af1 = (const uint32_t*)&a1;
            #pragma unroll
            for (int nt = 0; nt < 8; nt++) {
                const uint32_t* bf = (const uint32_t*)&bv[nt];
                mma_f16(acc[0][nt], af0, bf);
                mma_f16(acc[1][nt], af1, bf);
            }
        }
    }

    // ---------------- epilogue ----------------
    #pragma unroll
    for (int mt = 0; mt < 2; mt++) {
        const int b16 = wmB + mt;
        const int r0 = m0 + b16 * 16 + grp;
        const int r1 = r0 + 8;
        float pw0 = 1.0f, pw1 = 1.0f;
        if (MODE == 0) {
            pw0 = (r0 < N_ATOMS) ? combW[p * NSPECIES + species[r0]] : 0.0f;
            pw1 = (r1 < N_ATOMS) ? combW[p * NSPECIES + species[r1]] : 0.0f;
        }
        #pragma unroll
        for (int nt = 0; nt < 8; nt++) {
            const int c = (nh * 16 + wnB + nt) * 8 + tig * 2;   // global hidden col
            float x0 = silu(acc[mt][nt][0] * pw0);
            float x1 = silu(acc[mt][nt][1] * pw0);
            float x2 = silu(acc[mt][nt][2] * pw1);
            float x3 = silu(acc[mt][nt][3] * pw1);
            __half2 v01 = __floats2half2_rn(x0, x1);
            __half2 v23 = __floats2half2_rn(x2, x3);
            if (MODE == 0) {
                // write straight into fragment-major h1 (A of GEMM1)
                const int kt1 = c >> 5, kmma = (c >> 4) & 1, khalf = (c >> 3) & 1;
                size_t idx = (size_t)(p * MBLK64 + b64) * (KT1 * 1024);
                size_t sub = (size_t)(kt1 * 4 + b16);
                sub = sub * 2 + kmma;
                sub = sub * 32 + lane;
                uint32_t* base = g_h1f + idx + sub * 4;
                base[2 * khalf    ] = *(uint32_t*)&v01;
                base[2 * khalf + 1] = *(uint32_t*)&v23;
            } else {
                __half* C = g_h2h + (size_t)p * N_ATOMS * HIDDEN;
                if (r0 < N_ATOMS) *(uint32_t*)&C[(size_t)r0 * HIDDEN + c] = *(uint32_t*)&v01;
                if (r1 < N_ATOMS) *(uint32_t*)&C[(size_t)r1 * HIDDEN + c] = *(uint32_t*)&v23;
            }
        }
    }
}

// ---------------- final dot + segment sum ----------------
__global__ void zero_out_kernel(float* out) {
    if (threadIdx.x < N_STRUCT) out[threadIdx.x] = 0.0f;
}

__global__ void reduce_kernel(const float* __restrict__ W2,
                              const int* __restrict__ sid,
                              float* __restrict__ out) {
    const int a = blockIdx.x;
    const int t = threadIdx.x;
    float v = 0.0f;
    #pragma unroll
    for (int p = 0; p < NPSEUDO; p++)
        v += __half2float(g_h2h[((size_t)p * N_ATOMS + a) * HIDDEN + t]) * W2[p * HIDDEN + t];

    __shared__ float red[8];
    #pragma unroll
    for (int o = 16; o > 0; o >>= 1) v += __shfl_down_sync(0xffffffffu, v, o);
    if ((t & 31) == 0) red[t >> 5] = v;
    __syncthreads();
    if (t < 8) {
        float s = red[t];
        #pragma unroll
        for (int o = 4; o > 0; o >>= 1) s += __shfl_down_sync(0xffu, s, o);
        if (t == 0) atomicAdd(&out[sid[a]], s);
    }
}

// ---------------- launch ----------------
extern "C" void kernel_launch(void* const* d_in, const int* in_sizes, int n_in,
                              void* d_out, int out_size) {
    const float* c0      = (const float*)d_in[0];
    const float* c1      = (const float*)d_in[1];
    const float* c2      = (const float*)d_in[2];
    const float* c3      = (const float*)d_in[3];
    const int*   species = (const int*)d_in[4];
    const int*   sid     = (const int*)d_in[5];
    const float* combW   = (const float*)d_in[6];
    const float* W0      = (const float*)d_in[7];
    const float* W1      = (const float*)d_in[8];
    const float* W2      = (const float*)d_in[9];
    float* out = (float*)d_out;

    static bool attr_set = false;
    if (!attr_set) {
        cudaFuncSetAttribute(gemm_f16_kernel<KT0, 0>,
                             cudaFuncAttributeMaxDynamicSharedMemorySize, G_DSMEM);
        cudaFuncSetAttribute(gemm_f16_kernel<KT1, 1>,
                             cudaFuncAttributeMaxDynamicSharedMemorySize, G_DSMEM);
        attr_set = true;
    }

    {
        dim3 g(NPACK, NPSEUDO);
        convert_w0_kernel<<<g, 256>>>(W0);
    }
    {
        dim3 g(HIDDEN, NPSEUDO);
        convert_w1_kernel<<<g, 256>>>(W1);
    }

    features_kernel<<<APAD, 256>>>(c0, c1, c2, c3);

    {
        dim3 g(NPSEUDO * 2, MBLK64);
        gemm_f16_kernel<KT0, 0><<<g, 128, G_DSMEM>>>(combW, species);
        gemm_f16_kernel<KT1, 1><<<g, 128, G_DSMEM>>>(combW, species);
    }

    zero_out_kernel<<<1, 128>>>(out);
    reduce_kernel<<<N_ATOMS, 256>>>(W2, sid, out);
}